// round 2
// baseline (speedup 1.0000x reference)
#include <cuda_runtime.h>
#include <math.h>

#define NN  100000      // nodes
#define NE  1600000     // edges (without self loops)
#define NT  (NE + NN)   // edges + self loops
#define HID 64          // feature width of both layers' outputs

// ---------------- scratch (device globals; no allocation allowed) ----------
__device__ float    g_H  [NN * HID];   // h of current layer (post-GEMM)
__device__ float    g_ACC[NN * HID];   // scatter accumulator
__device__ float    g_H2 [NN * HID];   // layer-1 output (input to layer 2)
__device__ float    g_AS [NN];
__device__ float    g_AD [NN];
__device__ unsigned g_Mi [NN];         // ordered-uint running max
__device__ float    g_Mf [NN];         // decoded float max
__device__ float    g_DEN[NN];         // softmax denominator

// monotone float <-> uint encoding for atomicMax on floats (incl. negatives)
__device__ __forceinline__ unsigned enc_f(float f) {
    unsigned u = __float_as_uint(f);
    return (u & 0x80000000u) ? ~u : (u | 0x80000000u);
}
__device__ __forceinline__ float dec_f(unsigned u) {
    return (u & 0x80000000u) ? __uint_as_float(u & 0x7FFFFFFFu)
                             : __uint_as_float(~u);
}

// ---------------- kernels --------------------------------------------------

// reset accumulator / denom / running-max
__global__ void k_init() {
    int i = blockIdx.x * blockDim.x + threadIdx.x;
    if (i < NN * HID) g_ACC[i] = 0.f;
    if (i < NN) {
        g_Mi[i]  = 0x007FFFFFu;  // enc_f(-inf)
        g_DEN[i] = 0.f;
    }
}

// fused  H = X @ W^T,  AS = H @ a_src,  AD = H @ a_dst
// block: 256 threads = 4 nodes x 64 features
template <int K>
__global__ void k_gemm(const float* __restrict__ X,
                       const float* __restrict__ W,
                       const float* __restrict__ a_s,
                       const float* __restrict__ a_d,
                       float* __restrict__ Hout) {
    __shared__ float sW[K * HID];         // transposed: sW[k*64 + j]
    __shared__ float sX[4 * K];
    __shared__ float sR[4][2][2];         // [node][warp-in-node][src/dst]

    const int tid = threadIdx.x;
    const int f   = tid & 63;
    const int ty  = tid >> 6;
    const int node0 = blockIdx.x * 4;

    for (int i = tid; i < K * HID; i += 256) {
        int j = i / K, k = i - j * K;
        sW[k * HID + j] = W[i];           // coalesced gmem read, transposed store
    }
    for (int i = tid; i < 4 * K; i += 256) {
        int r = i / K;
        int node = node0 + r;
        sX[i] = (node < NN) ? X[(long long)node * K + (i - r * K)] : 0.f;
    }
    __syncthreads();

    float acc = 0.f;
    #pragma unroll 16
    for (int k = 0; k < K; k++)
        acc += sX[ty * K + k] * sW[k * HID + f];   // sX broadcast, sW conflict-free

    float vs = acc * a_s[f];
    float vd = acc * a_d[f];
    #pragma unroll
    for (int off = 16; off; off >>= 1) {
        vs += __shfl_down_sync(0xFFFFFFFFu, vs, off);
        vd += __shfl_down_sync(0xFFFFFFFFu, vd, off);
    }
    int w = (tid >> 5) & 1;
    if ((tid & 31) == 0) { sR[ty][w][0] = vs; sR[ty][w][1] = vd; }
    __syncthreads();

    int node = node0 + ty;
    if (node < NN) {
        Hout[(long long)node * HID + f] = acc;
        if (f == 0) {
            g_AS[node] = sR[ty][0][0] + sR[ty][1][0];
            g_AD[node] = sR[ty][0][1] + sR[ty][1][1];
        }
    }
}

// segment max of leaky-relu edge logits (one thread per edge, self-loops appended)
__global__ void k_emax(const int* __restrict__ src, const int* __restrict__ dst) {
    int i = blockIdx.x * blockDim.x + threadIdx.x;
    if (i >= NT) return;
    int s, d;
    if (i < NE) { s = src[i]; d = dst[i]; } else { s = d = i - NE; }
    float e = g_AS[s] + g_AD[d];
    e = (e > 0.f) ? e : 0.2f * e;
    atomicMax(&g_Mi[d], enc_f(e));
}

// decode running max to float
__global__ void k_dec() {
    int i = blockIdx.x * blockDim.x + threadIdx.x;
    if (i < NN) g_Mf[i] = dec_f(g_Mi[i]);
}

// per-edge accumulate: one warp per edge, 2 features per lane
__global__ void k_eacc(const int* __restrict__ src, const int* __restrict__ dst,
                       const float* __restrict__ Hin) {
    int gw   = (blockIdx.x * blockDim.x + threadIdx.x) >> 5;
    int lane = threadIdx.x & 31;
    if (gw >= NT) return;
    int s, d;
    if (gw < NE) { s = src[gw]; d = dst[gw]; } else { s = d = gw - NE; }
    float e = g_AS[s] + g_AD[d];
    e = (e > 0.f) ? e : 0.2f * e;
    float ex = expf(e - g_Mf[d]);
    if (lane == 0) atomicAdd(&g_DEN[d], ex);
    const float2* hp = reinterpret_cast<const float2*>(Hin + (long long)s * HID);
    float2 h = hp[lane];                               // coalesced 256B row read
    atomicAdd(&g_ACC[(long long)d * HID + 2 * lane    ], h.x * ex);
    atomicAdd(&g_ACC[(long long)d * HID + 2 * lane + 1], h.y * ex);
}

// layer-1 finalize: H2 = relu(ACC / DEN + b1)
__global__ void k_fin1(const float* __restrict__ b) {
    int i = blockIdx.x * blockDim.x + threadIdx.x;
    if (i >= NN * HID) return;
    int node = i >> 6, f = i & 63;
    float v = g_ACC[i] / g_DEN[node] + b[f];
    g_H2[i] = fmaxf(v, 0.f);
}

// zero the 64-float output
__global__ void k_zero(float* __restrict__ out) {
    if (threadIdx.x < HID) out[threadIdx.x] = 0.f;
}

// layer-2 finalize + global mean pool: out[f] = mean_i(ACC/DEN) + b2[f]
__global__ void k_fin2(const float* __restrict__ b, float* __restrict__ out) {
    int f = threadIdx.x;                 // 64 threads
    float local = 0.f;
    for (int i = blockIdx.x; i < NN; i += gridDim.x)
        local += g_ACC[(long long)i * HID + f] / g_DEN[i];
    local *= (1.0f / NN);
    if (blockIdx.x == 0) local += b[f];
    atomicAdd(&out[f], local);
}

// ---------------- launch ----------------------------------------------------
extern "C" void kernel_launch(void* const* d_in, const int* in_sizes, int n_in,
                              void* d_out, int out_size) {
    const float* x   = (const float*)d_in[0];
    const int*   ei  = (const int*)  d_in[1];
    // d_in[2] = edge_attr (unused by reference)
    const float* W1  = (const float*)d_in[3];
    const float* as1 = (const float*)d_in[4];
    const float* ad1 = (const float*)d_in[5];
    const float* b1  = (const float*)d_in[6];
    const float* W2  = (const float*)d_in[7];
    const float* as2 = (const float*)d_in[8];
    const float* ad2 = (const float*)d_in[9];
    const float* b2  = (const float*)d_in[10];
    float* out = (float*)d_out;

    const int* src = ei;
    const int* dst = ei + NE;

    float *pH, *pH2;
    cudaGetSymbolAddress((void**)&pH,  g_H);
    cudaGetSymbolAddress((void**)&pH2, g_H2);

    const int gInit  = (NN * HID + 255) / 256;
    const int gN4    = (NN + 3) / 4;
    const int gE1    = (NT + 255) / 256;
    const int gEW    = (NT + 7) / 8;          // 8 warps / 256-thread block
    const int gNode  = (NN + 255) / 256;

    // ---- layer 1 ----
    k_init<<<gInit, 256>>>();
    k_gemm<128><<<gN4, 256>>>(x, W1, as1, ad1, pH);
    k_emax<<<gE1, 256>>>(src, dst);
    k_dec<<<gNode, 256>>>();
    k_eacc<<<gEW, 256>>>(src, dst, pH);
    k_fin1<<<gInit, 256>>>(b1);

    // ---- layer 2 ----
    k_init<<<gInit, 256>>>();
    k_gemm<64><<<gN4, 256>>>(pH2, W2, as2, ad2, pH);
    k_emax<<<gE1, 256>>>(src, dst);
    k_dec<<<gNode, 256>>>();
    k_eacc<<<gEW, 256>>>(src, dst, pH);

    // ---- global mean pool ----
    k_zero<<<1, 64>>>(out);
    k_fin2<<<1024, 64>>>(b2, out);
}

// round 4
// speedup vs baseline: 1.1904x; 1.1904x over previous
#include <cuda_runtime.h>
#include <math.h>

#define NN  100000      // nodes
#define NE  1600000     // edges (without self loops)
#define NT  (NE + NN)   // edges + self loops
#define HID 64

#define SCAN_BLKS ((NN + 1023) / 1024)   // 98

// ---------------- scratch (device globals) ----------------------------------
__device__ float g_H  [NN * HID];   // post-GEMM features of current layer
__device__ float g_O  [NN * HID];   // aggregated output of current layer
__device__ float g_AS [NN];
__device__ float g_AD [NN];
__device__ int   g_deg   [NN];
__device__ int   g_rowptr[NN + 1];
__device__ int   g_cur   [NN];
__device__ int   g_bsum  [SCAN_BLKS];
__device__ int   g_boff  [SCAN_BLKS];
__device__ int   g_srcs  [NT];      // CSR-sorted source indices

// ---------------- CSR build --------------------------------------------------
__global__ void k_deg0() {
    int i = blockIdx.x * blockDim.x + threadIdx.x;
    if (i < NN) g_deg[i] = 0;
}

__global__ void k_count(const int* __restrict__ dst) {
    int i = blockIdx.x * blockDim.x + threadIdx.x;
    if (i >= NT) return;
    int d = (i < NE) ? dst[i] : i - NE;
    atomicAdd(&g_deg[d], 1);
}

// per-block exclusive scan (1024 elems/block) + block sums
__global__ void k_scan1() {
    __shared__ int s[1024];
    int tid = threadIdx.x;
    int i = blockIdx.x * 1024 + tid;
    int v = (i < NN) ? g_deg[i] : 0;
    s[tid] = v;
    __syncthreads();
    #pragma unroll
    for (int off = 1; off < 1024; off <<= 1) {
        int t = (tid >= off) ? s[tid - off] : 0;
        __syncthreads();
        s[tid] += t;
        __syncthreads();
    }
    if (i < NN) g_rowptr[i] = s[tid] - v;         // within-block exclusive
    if (tid == 1023) g_bsum[blockIdx.x] = s[1023];
}

__global__ void k_scan2() {
    if (threadIdx.x == 0) {
        int acc = 0;
        for (int b = 0; b < SCAN_BLKS; b++) { g_boff[b] = acc; acc += g_bsum[b]; }
    }
}

__global__ void k_scan3() {
    int i = blockIdx.x * blockDim.x + threadIdx.x;
    if (i < NN) {
        int r = g_rowptr[i] + g_boff[i >> 10];
        g_rowptr[i] = r;
        g_cur[i]    = r;
    }
    if (i == 0) g_rowptr[NN] = NT;
}

__global__ void k_scatter(const int* __restrict__ src, const int* __restrict__ dst) {
    int i = blockIdx.x * blockDim.x + threadIdx.x;
    if (i >= NT) return;
    int s, d;
    if (i < NE) { s = src[i]; d = dst[i]; } else { s = d = i - NE; }
    int pos = atomicAdd(&g_cur[d], 1);
    g_srcs[pos] = s;
}

// ---------------- fused GEMM + attention projections -------------------------
// H = X @ W^T, AS = H @ a_src, AD = H @ a_dst. 256 thr = 4 nodes x 64 feats.
template <int K>
__global__ void k_gemm(const float* __restrict__ X,
                       const float* __restrict__ W,
                       const float* __restrict__ a_s,
                       const float* __restrict__ a_d,
                       float* __restrict__ Hout) {
    __shared__ float sW[K * HID];
    __shared__ float sX[4 * K];
    __shared__ float sR[4][2][2];

    const int tid = threadIdx.x;
    const int f   = tid & 63;
    const int ty  = tid >> 6;
    const int node0 = blockIdx.x * 4;

    for (int i = tid; i < K * HID; i += 256) {
        int j = i / K, k = i - j * K;
        sW[k * HID + j] = W[i];
    }
    for (int i = tid; i < 4 * K; i += 256) {
        int r = i / K;
        int node = node0 + r;
        sX[i] = (node < NN) ? X[(long long)node * K + (i - r * K)] : 0.f;
    }
    __syncthreads();

    float acc = 0.f;
    #pragma unroll 16
    for (int k = 0; k < K; k++)
        acc += sX[ty * K + k] * sW[k * HID + f];

    float vs = acc * a_s[f];
    float vd = acc * a_d[f];
    #pragma unroll
    for (int off = 16; off; off >>= 1) {
        vs += __shfl_down_sync(0xFFFFFFFFu, vs, off);
        vd += __shfl_down_sync(0xFFFFFFFFu, vd, off);
    }
    int w = (tid >> 5) & 1;
    if ((tid & 31) == 0) { sR[ty][w][0] = vs; sR[ty][w][1] = vd; }
    __syncthreads();

    int node = node0 + ty;
    if (node < NN) {
        Hout[(long long)node * HID + f] = acc;
        if (f == 0) {
            g_AS[node] = sR[ty][0][0] + sR[ty][1][0];
            g_AD[node] = sR[ty][0][1] + sR[ty][1][1];
        }
    }
}

// ---------------- fused segment softmax + weighted aggregation ---------------
// One warp per dst node. No float atomics; one coalesced float2 store per row.
template <int RELU>
__global__ void k_aggr(const float* __restrict__ Hin,
                       const float* __restrict__ b,
                       float* __restrict__ Hout) {
    int gw   = (blockIdx.x * blockDim.x + threadIdx.x) >> 5;
    int lane = threadIdx.x & 31;
    if (gw >= NN) return;

    const int beg = g_rowptr[gw];
    const int end = g_rowptr[gw + 1];
    const float ad = g_AD[gw];

    // phase 1: segment max (lane-parallel over edges)
    float m = -1e30f;
    for (int j = beg + lane; j < end; j += 32) {
        int s = g_srcs[j];
        float e = g_AS[s] + ad;
        e = (e > 0.f) ? e : 0.2f * e;
        m = fmaxf(m, e);
    }
    #pragma unroll
    for (int off = 16; off; off >>= 1)
        m = fmaxf(m, __shfl_xor_sync(0xFFFFFFFFu, m, off));

    // phase 2: exp-sum + weighted feature accumulation (edge-sequential,
    // lane-parallel over 64 features, unrolled x2 for MLP)
    float acc0 = 0.f, acc1 = 0.f, den = 0.f;
    int j = beg;
    for (; j + 2 <= end; j += 2) {
        int s0 = g_srcs[j], s1 = g_srcs[j + 1];
        float2 h0 = reinterpret_cast<const float2*>(Hin + (long long)s0 * HID)[lane];
        float2 h1 = reinterpret_cast<const float2*>(Hin + (long long)s1 * HID)[lane];
        float e0 = g_AS[s0] + ad;  e0 = (e0 > 0.f) ? e0 : 0.2f * e0;
        float e1 = g_AS[s1] + ad;  e1 = (e1 > 0.f) ? e1 : 0.2f * e1;
        float x0 = __expf(e0 - m);
        float x1 = __expf(e1 - m);
        den  += x0 + x1;
        acc0 += h0.x * x0 + h1.x * x1;
        acc1 += h0.y * x0 + h1.y * x1;
    }
    if (j < end) {
        int s0 = g_srcs[j];
        float2 h0 = reinterpret_cast<const float2*>(Hin + (long long)s0 * HID)[lane];
        float e0 = g_AS[s0] + ad;  e0 = (e0 > 0.f) ? e0 : 0.2f * e0;
        float x0 = __expf(e0 - m);
        den  += x0;
        acc0 += h0.x * x0;
        acc1 += h0.y * x0;
    }

    float inv = 1.0f / den;
    float v0 = acc0 * inv + b[2 * lane];
    float v1 = acc1 * inv + b[2 * lane + 1];
    if (RELU) { v0 = fmaxf(v0, 0.f); v1 = fmaxf(v1, 0.f); }
    reinterpret_cast<float2*>(Hout + (long long)gw * HID)[lane] = make_float2(v0, v1);
}

// ---------------- global mean pool -------------------------------------------
__global__ void k_zero(float* __restrict__ out) {
    if (threadIdx.x < HID) out[threadIdx.x] = 0.f;
}

__global__ void k_mean(const float* __restrict__ Hin, float* __restrict__ out) {
    int f = threadIdx.x;                 // 64 threads
    float local = 0.f;
    for (int i = blockIdx.x; i < NN; i += gridDim.x)
        local += Hin[(long long)i * HID + f];
    atomicAdd(&out[f], local * (1.0f / NN));
}

// ---------------- launch ------------------------------------------------------
extern "C" void kernel_launch(void* const* d_in, const int* in_sizes, int n_in,
                              void* d_out, int out_size) {
    const float* x   = (const float*)d_in[0];
    const int*   ei  = (const int*)  d_in[1];
    const float* W1  = (const float*)d_in[3];
    const float* as1 = (const float*)d_in[4];
    const float* ad1 = (const float*)d_in[5];
    const float* b1  = (const float*)d_in[6];
    const float* W2  = (const float*)d_in[7];
    const float* as2 = (const float*)d_in[8];
    const float* ad2 = (const float*)d_in[9];
    const float* b2  = (const float*)d_in[10];
    float* out = (float*)d_out;

    const int* src = ei;
    const int* dst = ei + NE;

    float *pH, *pO;
    cudaGetSymbolAddress((void**)&pH, g_H);
    cudaGetSymbolAddress((void**)&pO, g_O);

    const int gNode = (NN + 255) / 256;
    const int gEdge = (NT + 255) / 256;
    const int gN4   = (NN + 3) / 4;
    const int gAggr = (NN + 7) / 8;          // 8 warps / 256-thread block

    // ---- build CSR (used by both layers) ----
    k_deg0   <<<gNode, 256>>>();
    k_count  <<<gEdge, 256>>>(dst);
    k_scan1  <<<SCAN_BLKS, 1024>>>();
    k_scan2  <<<1, 32>>>();
    k_scan3  <<<gNode, 256>>>();
    k_scatter<<<gEdge, 256>>>(src, dst);

    // ---- layer 1 ----
    k_gemm<128><<<gN4, 256>>>(x, W1, as1, ad1, pH);
    k_aggr<1>  <<<gAggr, 256>>>(pH, b1, pO);

    // ---- layer 2 ----
    k_gemm<64><<<gN4, 256>>>(pO, W2, as2, ad2, pH);
    k_aggr<0>  <<<gAggr, 256>>>(pH, b2, pO);

    // ---- global mean pool ----
    k_zero<<<1, 64>>>(out);
    k_mean<<<1024, 64>>>(pO, out);
}